// round 11
// baseline (speedup 1.0000x reference)
#include <cuda_runtime.h>

#define BN 16
#define CN 1024
#define TN 16
#define PN 360          // H*W
#define KN 120
#define OUTROWS 482     // 1 + 120 + 1 + 360
#define CT 64           // tile: c extent
#define PT 64           // tile: p extent
#define NCT (CN / CT)   // 16 c-tiles
#define NPT 6           // ceil(PN/PT)
#define PLANE (TN * PN) // 5760 floats per (b,c) plane
#define TS 68           // K1 tile row stride (floats)

// scratch (no allocations allowed)
__device__ float g_partial[BN][NCT][PN];

// ---------------------------------------------------------------------------
// K1: single fused pass over x[b, :, 0:2, :]  (round-8 geometry).
// Lanes 0-15 FMA frame-0 quads into registers; lanes 16-31 STS.128 frame-1
// quads into a [c][p] tile, then transposed STG.128 to out rows 122+p.
// Blocks (0, 0, b) additionally copy the two cls rows.
// ---------------------------------------------------------------------------
__global__ void __launch_bounds__(256)
fused_kernel(const float* __restrict__ x, const float* __restrict__ cls,
             float* __restrict__ out) {
    __shared__ float tile[CT][TS];     // frame-1 only, [cc][pp]
    __shared__ float scls[CT];
    __shared__ float sacc[8][PT];
    const int tid = threadIdx.x;
    const int b  = blockIdx.z;
    const int c0 = blockIdx.y * CT;
    const int p0 = blockIdx.x * PT;
    const float* xplane = x + ((size_t)b * CN + c0) * PLANE;

    if (tid < CT) scls[tid] = cls[(size_t)b * TN * CN + c0 + tid];
    __syncthreads();

    const int q  = tid & 31;
    const int wg = tid >> 5;
    const int f  = q >> 4;            // lane 0-15: frame 0, lane 16-31: frame 1
    const int pq = q & 15;
    const int p  = p0 + 4 * pq;
    const bool valid = (p < PN);

    float4 acc = make_float4(0.f, 0.f, 0.f, 0.f);
#pragma unroll
    for (int it = 0; it < 8; ++it) {               // cc = wg + it*8
        int cc = wg + it * 8;
        float4 v = make_float4(0.f, 0.f, 0.f, 0.f);
        if (valid)
            v = *(const float4*)(xplane + (size_t)cc * PLANE + f * PN + p);
        if (f == 0) {
            float s = scls[cc];
            acc.x = fmaf(s, v.x, acc.x);
            acc.y = fmaf(s, v.y, acc.y);
            acc.z = fmaf(s, v.z, acc.z);
            acc.w = fmaf(s, v.w, acc.w);
        } else {
            *(float4*)&tile[cc][4 * pq] = v;
        }
    }
    if (f == 0)
        *(float4*)&sacc[wg][4 * pq] = acc;

    // cls rows while waiting: out[b,0,:]=cls[b,0,:], out[b,121,:]=cls[b,1,:]
    if (blockIdx.x == 0 && blockIdx.y == 0) {
        const float4* c4 = (const float4*)(cls + (size_t)b * TN * CN);
        float4* o4 = (float4*)(out + (size_t)b * OUTROWS * CN);
        o4[tid] = c4[tid];                               // row 0
        o4[(size_t)121 * 256 + tid] = c4[256 + tid];     // row 121
    }
    __syncthreads();

    if (tid < PT) {
        int pp = p0 + tid;
        if (pp < PN) {
            float a = 0.f;
#pragma unroll
            for (int w = 0; w < 8; ++w) a += sacc[w][tid];
            g_partial[b][blockIdx.y][pp] = a;
        }
    }

#pragma unroll
    for (int it = 0; it < 4; ++it) {
        int idx = tid + it * 256;
        int pl = idx >> 4, cq = idx & 15;
        int pp = p0 + pl;
        if (pp < PN) {
            float4 v;
            v.x = tile[4 * cq + 0][pl];
            v.y = tile[4 * cq + 1][pl];
            v.z = tile[4 * cq + 2][pl];
            v.w = tile[4 * cq + 3][pl];
            __stcs((float4*)(out + ((size_t)b * OUTROWS + 122 + pp) * CN + c0 + 4 * cq), v);
        }
    }
}

// ---------------------------------------------------------------------------
// K2: fused rank + frame-0 scatter. Every block redundantly (deterministically,
// same summation order -> bitwise-identical scores) reduces g_partial[b] and
// ranks its own 64 p's (exact stable descending rank = jax top_k tie-break:
// #greater + #equal-with-smaller-index; monotone softmax/max transforms cannot
// change the ordering). x-tile loads are issued into registers first so their
// latency covers the rank math.
//   out[b, 1+rank[p], c] = x[b,c,0,p]   for rank[p] < K
// ---------------------------------------------------------------------------
__global__ void __launch_bounds__(256)
scatter_rank_kernel(const float* __restrict__ x, float* __restrict__ out) {
    __shared__ float s[384];            // [0,360) scores, [360,384) zero pad
    __shared__ float tile[PT][CT + 1];
    __shared__ int   rk[PT];
    __shared__ int   cnt4[4][PT];
    const int tid = threadIdx.x;
    const int b  = blockIdx.z;
    const int c0 = blockIdx.y * CT;
    const int p0 = blockIdx.x * PT;
    const float* xplane = x + ((size_t)b * CN + c0) * PLANE;   // t = 0

    // 1) issue x loads into registers (latency hidden by rank work below)
    float4 vreg[4];
#pragma unroll
    for (int it = 0; it < 4; ++it) {
        int idx = tid + it * 256;
        int pq = idx & 15;
        int cc = idx >> 4;
        int p = p0 + 4 * pq;
        vreg[it] = make_float4(0.f, 0.f, 0.f, 0.f);
        if (p < PN)
            vreg[it] = *(const float4*)(xplane + (size_t)cc * PLANE + p);
    }

    // 2) reduce partials -> scores (identical order in every block)
    if (tid < 384 - PN) s[PN + tid] = 0.f;     // zero ONLY the pad [360,384)
    for (int p = tid; p < PN; p += 256) {
        float a = 0.f;
#pragma unroll
        for (int k = 0; k < NCT; ++k) a += g_partial[b][k][p];
        s[p] = a;
    }
    __syncthreads();

    // 3) rank this block's 64 p's: 4 groups x 90 comparisons
    {
        int pidx = tid & 63, g = tid >> 6;
        int p = p0 + pidx;
        float v = s[p];                   // padded: safe even if p >= PN
        int cnt = 0;
#pragma unroll 6
        for (int j = 0; j < 90; ++j) {
            int qq = g * 90 + j;
            float sq = s[qq];
            cnt += (sq > v) || (sq == v && qq < p);
        }
        cnt4[g][pidx] = cnt;
    }

    // 4) park x data in smem (transposed)
#pragma unroll
    for (int it = 0; it < 4; ++it) {
        int idx = tid + it * 256;
        int pq = idx & 15;
        int cc = idx >> 4;
        tile[4 * pq + 0][cc] = vreg[it].x;
        tile[4 * pq + 1][cc] = vreg[it].y;
        tile[4 * pq + 2][cc] = vreg[it].z;
        tile[4 * pq + 3][cc] = vreg[it].w;
    }
    __syncthreads();

    if (tid < PT) {
        int p = p0 + tid;
        rk[tid] = (p < PN)
            ? (cnt4[0][tid] + cnt4[1][tid]) + (cnt4[2][tid] + cnt4[3][tid])
            : KN;
    }
    __syncthreads();

    // 5) scatter selected rows, STG.128 along c
#pragma unroll
    for (int it = 0; it < 4; ++it) {
        int idx = tid + it * 256;
        int pl = idx >> 4, cq = idx & 15;
        int r = rk[pl];
        if (r >= KN) continue;
        float4 v;
        v.x = tile[pl][4 * cq + 0];
        v.y = tile[pl][4 * cq + 1];
        v.z = tile[pl][4 * cq + 2];
        v.w = tile[pl][4 * cq + 3];
        __stcs((float4*)(out + ((size_t)b * OUTROWS + 1 + r) * CN + c0 + 4 * cq), v);
    }
}

extern "C" void kernel_launch(void* const* d_in, const int* in_sizes, int n_in,
                              void* d_out, int out_size) {
    const float* x   = (const float*)d_in[0];   // [16,1024,16,12,30] f32
    const float* cls = (const float*)d_in[1];   // [16,16,1024] f32
    float* out = (float*)d_out;                 // [16,482,1024] f32

    fused_kernel<<<dim3(NPT, NCT, BN), 256>>>(x, cls, out);
    scatter_rank_kernel<<<dim3(NPT, NCT, BN), 256>>>(x, out);
}